// round 1
// baseline (speedup 1.0000x reference)
#include <cuda_runtime.h>
#include <cuda_bf16.h>
#include <math_constants.h>

// Shapes (fixed for this problem)
#define B  32
#define S  4096
#define H  1024
#define D  2048   // 2*H

// Scratch (device globals; no allocation allowed)
__device__ float g_vpart[4][B * D];   // h-split partials of v = W^T hidden
__device__ float g_v[B * D];
__device__ float g_energy[B * S];

// ---------------------------------------------------------------------------
// Kernel 1: v_part[hs][b][d] = sum_{h in split hs} hidden[b][h] * W[h][d]
// grid (8 d-blocks, 4 b-groups, 4 h-splits), block 256. W element is loaded
// once and reused across 8 batches in registers (keeps L2 W traffic ~32MB).
// ---------------------------------------------------------------------------
__global__ void k_vpart(const float* __restrict__ hidden,
                        const float* __restrict__ W) {
    const int tid  = threadIdx.x;
    const int d    = blockIdx.x * 256 + tid;
    const int bg   = blockIdx.y;          // batch group of 8
    const int hs   = blockIdx.z;          // h split of 256

    __shared__ float hsm[8][256];
    for (int idx = tid; idx < 8 * 256; idx += 256) {
        int bl = idx >> 8, hl = idx & 255;
        hsm[bl][hl] = hidden[(bg * 8 + bl) * H + hs * 256 + hl];
    }
    __syncthreads();

    float acc[8];
#pragma unroll
    for (int j = 0; j < 8; ++j) acc[j] = 0.f;

    const float* Wp = W + (size_t)(hs * 256) * D + d;
#pragma unroll 4
    for (int hl = 0; hl < 256; ++hl) {
        float w = Wp[(size_t)hl * D];
#pragma unroll
        for (int j = 0; j < 8; ++j) acc[j] += hsm[j][hl] * w;
    }

#pragma unroll
    for (int j = 0; j < 8; ++j)
        g_vpart[hs][(bg * 8 + j) * D + d] = acc[j];
}

// ---------------------------------------------------------------------------
// Kernel 1b: v = sum of 4 h-split partials (deterministic, no atomics)
// ---------------------------------------------------------------------------
__global__ void k_vreduce() {
    int idx = blockIdx.x * blockDim.x + threadIdx.x;   // B*D threads
    if (idx < B * D) {
        g_v[idx] = g_vpart[0][idx] + g_vpart[1][idx]
                 + g_vpart[2][idx] + g_vpart[3][idx];
    }
}

// ---------------------------------------------------------------------------
// Kernel 2: energies[b][s] = dot(enc[b][s][:], v[b][:])
// blockDim 512 (16 warps). Each warp: loads v[b] once into 16 float4 regs,
// then processes 4 rows of enc (streamed with __ldcs), warp-reduces each dot.
// grid (S/64, B). enc: 1.07 GB single streaming pass -> HBM-bound.
// ---------------------------------------------------------------------------
__global__ __launch_bounds__(512) void k_energy(const float* __restrict__ enc) {
    const int b    = blockIdx.y;
    const int warp = threadIdx.x >> 5;
    const int lane = threadIdx.x & 31;
    const int s0   = blockIdx.x * 64 + warp * 4;

    // Load v[b] slice for this warp: 16 float4 per lane covers all 2048 floats
    const float4* v4 = reinterpret_cast<const float4*>(g_v + b * D);
    float4 vv[16];
#pragma unroll
    for (int i = 0; i < 16; ++i) vv[i] = v4[i * 32 + lane];

#pragma unroll
    for (int r = 0; r < 4; ++r) {
        const int s = s0 + r;
        const float4* e4 = reinterpret_cast<const float4*>(
            enc + ((size_t)b * S + s) * D);
        float acc = 0.f;
#pragma unroll
        for (int i = 0; i < 16; ++i) {
            float4 e = __ldcs(&e4[i * 32 + lane]);
            acc += e.x * vv[i].x + e.y * vv[i].y
                 + e.z * vv[i].z + e.w * vv[i].w;
        }
        // warp reduce
#pragma unroll
        for (int off = 16; off > 0; off >>= 1)
            acc += __shfl_xor_sync(0xFFFFFFFFu, acc, off);
        if (lane == 0) g_energy[b * S + s] = acc;
    }
}

// ---------------------------------------------------------------------------
// Kernel 3: per-batch softmax over S. One block per batch, 512 threads,
// 8 elems/thread. (Bias term dropped: constant per row, cancels in softmax.)
// ---------------------------------------------------------------------------
__global__ __launch_bounds__(512) void k_softmax(float* __restrict__ out) {
    const int b   = blockIdx.x;
    const int tid = threadIdx.x;
    __shared__ float red[16];

    float e[8];
    float mx = -CUDART_INF_F;
#pragma unroll
    for (int i = 0; i < 8; ++i) {
        e[i] = g_energy[b * S + tid + i * 512];
        mx = fmaxf(mx, e[i]);
    }
#pragma unroll
    for (int off = 16; off > 0; off >>= 1)
        mx = fmaxf(mx, __shfl_xor_sync(0xFFFFFFFFu, mx, off));
    if ((tid & 31) == 0) red[tid >> 5] = mx;
    __syncthreads();
    if (tid < 32) {
        float m = (tid < 16) ? red[tid] : -CUDART_INF_F;
#pragma unroll
        for (int off = 8; off > 0; off >>= 1)
            m = fmaxf(m, __shfl_xor_sync(0xFFFFFFFFu, m, off));
        if (tid == 0) red[0] = m;
    }
    __syncthreads();
    mx = red[0];
    __syncthreads();

    float sum = 0.f;
#pragma unroll
    for (int i = 0; i < 8; ++i) {
        e[i] = __expf(e[i] - mx);
        sum += e[i];
    }
#pragma unroll
    for (int off = 16; off > 0; off >>= 1)
        sum += __shfl_xor_sync(0xFFFFFFFFu, sum, off);
    if ((tid & 31) == 0) red[tid >> 5] = sum;
    __syncthreads();
    if (tid < 32) {
        float s = (tid < 16) ? red[tid] : 0.f;
#pragma unroll
        for (int off = 8; off > 0; off >>= 1)
            s += __shfl_xor_sync(0xFFFFFFFFu, s, off);
        if (tid == 0) red[0] = s;
    }
    __syncthreads();
    const float inv = 1.0f / red[0];

#pragma unroll
    for (int i = 0; i < 8; ++i)
        out[b * S + tid + i * 512] = e[i] * inv;
}

// ---------------------------------------------------------------------------
extern "C" void kernel_launch(void* const* d_in, const int* in_sizes, int n_in,
                              void* d_out, int out_size) {
    const float* hidden = (const float*)d_in[0];   // [B,H]
    const float* enc    = (const float*)d_in[1];   // [B,S,2H]
    const float* W      = (const float*)d_in[2];   // [H,2H]
    // d_in[3] = bias: constant per row -> cancels in softmax, unused.
    float* out = (float*)d_out;                    // [B,1,S]

    k_vpart<<<dim3(D / 256, B / 8, 4), 256>>>(hidden, W);
    k_vreduce<<<(B * D + 255) / 256, 256>>>();
    k_energy<<<dim3(S / 64, B), 512>>>(enc);
    k_softmax<<<B, 512>>>(out);
}